// round 4
// baseline (speedup 1.0000x reference)
#include <cuda_runtime.h>
#include <cuda_fp16.h>
#include <cstdint>
#include <cstddef>

#define BB   8
#define NN   4096
#define KK   32
#define DD   64
#define CIN  67
#define MLPC 64
#define P1C  128
#define P2C  64
#define R2   0.04f
#define EPSF 1e-5f

// Scratch (device globals; no allocation allowed)
__device__ __half  Th_g[BB * NN * MLPC];   // fp16 s*(pts·Wd + xyz·Wx + b), n-major rows (128B)
__device__ float4  P4_g[BB * NN];          // (x, y, z, ||p||^2)
__device__ float   np_g[BB * NN * MLPC];   // max-pooled features, n-major rows
__device__ float4  sC4_g[MLPC];            // {s*Wx0, s*Wx1, s*Wx2, bt - s*rm}

// ---- f32x2 packed helpers -------------------------------------------------
__device__ __forceinline__ void ffma2(unsigned long long& d,
                                      unsigned long long a,
                                      unsigned long long b) {
    asm("fma.rn.f32x2 %0, %1, %2, %0;" : "+l"(d) : "l"(a), "l"(b));
}
__device__ __forceinline__ void fadd2(unsigned long long& d, unsigned long long a) {
    asm("add.rn.f32x2 %0, %0, %1;" : "+l"(d) : "l"(a));
}
__device__ __forceinline__ unsigned long long pack2(float lo, float hi) {
    unsigned long long r;
    asm("mov.b64 %0, {%1, %2};" : "=l"(r) : "f"(lo), "f"(hi));
    return r;
}
__device__ __forceinline__ void unpack2(unsigned long long p, float& lo, float& hi) {
    asm("mov.b64 {%0, %1}, %2;" : "=f"(lo), "=f"(hi) : "l"(p));
}

// ---------------------------------------------------------------------------
// K1: precompute Th rows (fp16) + candidate table + sC4 constants
// block = 256 threads = 8 warps; block handles 32 points (warp does 4)
// ---------------------------------------------------------------------------
__global__ __launch_bounds__(256) void k_pre(
    const float* __restrict__ xyz, const float* __restrict__ pts,
    const float* __restrict__ W,   const float* __restrict__ bcv,
    const float* __restrict__ g,   const float* __restrict__ bt,
    const float* __restrict__ rm,  const float* __restrict__ rv)
{
    __shared__ float Wsh[CIN * MLPC];   // [c][o], s-folded: s[o]*W[o][c]
    __shared__ float s_sh[MLPC];
    __shared__ float bs_sh[MLPC];
    __shared__ float Xs[32 * 68];       // 32 points x 67 channels (pad 68)

    int tid = threadIdx.x;
    if (tid < MLPC) {
        float s = g[tid] / sqrtf(rv[tid] + EPSF);
        s_sh[tid]  = s;
        bs_sh[tid] = s * bcv[tid];
    }
    __syncthreads();

    for (int i = tid; i < CIN * MLPC; i += 256) {
        int c = i >> 6, o = i & 63;
        Wsh[i] = s_sh[o] * W[o * CIN + c];
    }

    int b  = blockIdx.x >> 7;              // grid = 8 * 128
    int m0 = (blockIdx.x & 127) << 5;      // 32 points per block
    for (int i = tid; i < 32 * CIN; i += 256) {
        int p = i & 31, c = i >> 5;
        float v = (c < DD) ? pts[(b * DD + c) * NN + m0 + p]
                           : xyz[(b * 3 + (c - DD)) * NN + m0 + p];
        Xs[p * 68 + c] = v;
    }
    __syncthreads();

    if (blockIdx.x == 0 && tid < MLPC) {
        sC4_g[tid] = make_float4(Wsh[64 * MLPC + tid], Wsh[65 * MLPC + tid],
                                 Wsh[66 * MLPC + tid],
                                 bt[tid] - s_sh[tid] * rm[tid]);
    }

    if (tid < 32) {
        float x = Xs[tid * 68 + 64], y = Xs[tid * 68 + 65], z = Xs[tid * 68 + 66];
        P4_g[b * NN + m0 + tid] = make_float4(x, y, z, fmaf(z, z, fmaf(y, y, x * x)));
    }

    int w = tid >> 5, lane = tid & 31;
#pragma unroll
    for (int pp = 0; pp < 4; pp++) {
        int p = w * 4 + pp;
        const float* Xw = &Xs[p * 68];
        unsigned long long acc = pack2(bs_sh[2 * lane], bs_sh[2 * lane + 1]);
#pragma unroll
        for (int c = 0; c < CIN; c++) {
            float xv = Xw[c];
            unsigned long long xx = pack2(xv, xv);
            unsigned long long wv =
                *(const unsigned long long*)&Wsh[c * MLPC + 2 * lane];
            ffma2(acc, wv, xx);
        }
        float a0, a1;
        unpack2(acc, a0, a1);
        int gm = b * NN + m0 + p;
        ((__half2*)Th_g)[(size_t)gm * 32 + lane] = __floats2half2_rn(a0, a1);
    }
}

// ---------------------------------------------------------------------------
// K2: warp-autonomous ball query + fp16 gather-max
// block = 256 threads = 8 warps = 8 queries; grid = 4096
// ---------------------------------------------------------------------------
__global__ __launch_bounds__(256) void k_ball()
{
    __shared__ int gi_sh[8][KK];

    int tid  = threadIdx.x;
    int w    = tid >> 5;
    int lane = tid & 31;

    int b  = blockIdx.x >> 9;                   // 512 blocks per batch
    int n  = ((blockIdx.x & 511) << 3) + w;
    int bN = b * NN;

    float4 q = P4_g[bN + n];

    int cnt = 0;
    float4 c = __ldg(&P4_g[bN + lane]);
#pragma unroll 1
    for (int base = 0; base < NN; base += 32) {
        int nb = (base + 32 < NN) ? base + 32 : base;
        float4 cn = __ldg(&P4_g[bN + nb + lane]);

        float dot  = fmaf(q.z, c.z, fmaf(q.y, c.y, q.x * c.x));
        float dist = q.w + c.w - 2.0f * dot;       // reference's exact form
        unsigned mask = __ballot_sync(0xffffffffu, dist <= R2);
        if (dist <= R2) {
            int pos = cnt + __popc(mask & ((1u << lane) - 1u));
            if (pos < KK) gi_sh[w][pos] = base + lane;
        }
        cnt += __popc(mask);
        if (cnt >= KK) break;
        c = cn;
    }
    __syncwarp();

    int cap   = (cnt < KK) ? cnt : KK;
    int gidx0 = gi_sh[w][0];

    __half2 mx = __float2half2_rn(-65504.0f);
#pragma unroll
    for (int j = 0; j < KK; j++) {
        int gj = (j < cap) ? gi_sh[w][j] : gidx0;
        const __half2* tr = ((const __half2*)Th_g) + (((size_t)(bN + gj)) << 5) + lane;
        mx = __hmax2(mx, __ldg(tr));
    }
    float2 m = __half22float2(mx);

    float4 a0 = sC4_g[2 * lane];
    float4 a1 = sC4_g[2 * lane + 1];
    float u0 = a0.w - fmaf(a0.z, q.z, fmaf(a0.y, q.y, a0.x * q.x));
    float u1 = a1.w - fmaf(a1.z, q.z, fmaf(a1.y, q.y, a1.x * q.x));

    float2 outv = make_float2(fmaxf(m.x + u0, 0.0f), fmaxf(m.y + u1, 0.0f));
    *(float2*)&np_g[((size_t)(bN + n)) * MLPC + 2 * lane] = outv;
}

// ---------------------------------------------------------------------------
// K3: pointwise resnet 64->128->64 + residual ReLU, f32x2 packed FMA
// ---------------------------------------------------------------------------
__global__ __launch_bounds__(128) void k_resnet(
    const float* __restrict__ W1, const float* __restrict__ b1,
    const float* __restrict__ g1, const float* __restrict__ bt1,
    const float* __restrict__ rm1, const float* __restrict__ rv1,
    const float* __restrict__ W2, const float* __restrict__ b2,
    const float* __restrict__ g2, const float* __restrict__ bt2,
    const float* __restrict__ rm2, const float* __restrict__ rv2,
    const float* __restrict__ pts, float* __restrict__ out)
{
    extern __shared__ float sm[];
    float* W1sh  = sm;                  // [128][64] row-major
    float* W2Tsh = sm + P1C * P2C;      // [o][p] (W2 transposed)
    float* s1sh  = W2Tsh + P1C * P2C;
    float* t1sh  = s1sh + P1C;
    float* s2sh  = t1sh + P1C;
    float* t2sh  = s2sh + P2C;

    int tid = threadIdx.x;
    for (int i = tid; i < P1C * P2C; i += 128) {
        W1sh[i] = W1[i];
        W2Tsh[(i & (P1C - 1)) * P2C + (i >> 7)] = W2[i];
    }
    if (tid < P1C) {
        float s = g1[tid] / sqrtf(rv1[tid] + EPSF);
        s1sh[tid] = s;
        t1sh[tid] = fmaf(s, b1[tid] - rm1[tid], bt1[tid]);
    }
    if (tid < P2C) {
        float s = g2[tid] / sqrtf(rv2[tid] + EPSF);
        s2sh[tid] = s;
        t2sh[tid] = fmaf(s, b2[tid] - rm2[tid], bt2[tid]);
    }
    __syncthreads();

    int pt = blockIdx.x * 128 + tid;
    int b  = pt >> 12;
    int n  = pt & (NN - 1);

    unsigned long long v2[32];
    {
        const ulonglong2* vr = (const ulonglong2*)(np_g + (size_t)pt * MLPC);
#pragma unroll
        for (int i = 0; i < 16; i++) {
            ulonglong2 t = vr[i];
            v2[2 * i] = t.x;
            v2[2 * i + 1] = t.y;
        }
    }

    unsigned long long ap[32];
#pragma unroll
    for (int i = 0; i < 32; i++) ap[i] = 0ull;

#pragma unroll 2
    for (int o = 0; o < P1C; o++) {
        const ulonglong2* w1r = (const ulonglong2*)(W1sh + o * P2C);
        unsigned long long hp0 = 0ull, hp1 = 0ull, hp2 = 0ull, hp3 = 0ull;
#pragma unroll
        for (int i = 0; i < 8; i++) {
            ulonglong2 wa = w1r[2 * i];
            ulonglong2 wb = w1r[2 * i + 1];
            ffma2(hp0, wa.x, v2[4 * i + 0]);
            ffma2(hp1, wa.y, v2[4 * i + 1]);
            ffma2(hp2, wb.x, v2[4 * i + 2]);
            ffma2(hp3, wb.y, v2[4 * i + 3]);
        }
        fadd2(hp0, hp1);
        fadd2(hp2, hp3);
        fadd2(hp0, hp2);
        float hl, hh;
        unpack2(hp0, hl, hh);
        float h  = hl + hh;
        float x1 = fmaxf(fmaf(s1sh[o], h, t1sh[o]), 0.0f);
        unsigned long long X = pack2(x1, x1);

        const ulonglong2* w2r = (const ulonglong2*)(W2Tsh + o * P2C);
#pragma unroll
        for (int i = 0; i < 16; i++) {
            ulonglong2 wt = w2r[i];
            ffma2(ap[2 * i + 0], wt.x, X);
            ffma2(ap[2 * i + 1], wt.y, X);
        }
    }

#pragma unroll
    for (int i = 0; i < 32; i++) {
        float a0, a1;
        unpack2(ap[i], a0, a1);
        int p0 = 2 * i, p1 = 2 * i + 1;
        float v0 = fmaf(s2sh[p0], a0, t2sh[p0]) + pts[(b * P2C + p0) * NN + n];
        float v1 = fmaf(s2sh[p1], a1, t2sh[p1]) + pts[(b * P2C + p1) * NN + n];
        out[(b * P2C + p0) * NN + n] = fmaxf(v0, 0.0f);
        out[(b * P2C + p1) * NN + n] = fmaxf(v1, 0.0f);
    }
}

// ---------------------------------------------------------------------------
// Launch
// ---------------------------------------------------------------------------
extern "C" void kernel_launch(void* const* d_in, const int* in_sizes, int n_in,
                              void* d_out, int out_size)
{
    (void)n_in; (void)out_size;

    const float* xyz = (const float*)d_in[0];
    const float* pts = (const float*)d_in[1];
    const float* W   = (const float*)d_in[2];
    const float* bcv = (const float*)d_in[3];
    const float* g   = (const float*)d_in[4];
    const float* bt  = (const float*)d_in[5];
    const float* rm  = (const float*)d_in[6];
    const float* rv  = (const float*)d_in[7];
    const float* W1  = (const float*)d_in[8];
    const float* b1  = (const float*)d_in[9];
    const float* g1  = (const float*)d_in[10];
    const float* bt1 = (const float*)d_in[11];
    const float* rm1 = (const float*)d_in[12];
    const float* rv1 = (const float*)d_in[13];
    const float* W2  = (const float*)d_in[14];
    const float* b2  = (const float*)d_in[15];
    const float* g2  = (const float*)d_in[16];
    const float* bt2 = (const float*)d_in[17];
    const float* rm2 = (const float*)d_in[18];
    const float* rv2 = (const float*)d_in[19];

    float* out = (float*)d_out;

    static const size_t smem3 =
        (size_t)(P1C * P2C * 2 + P1C * 2 + P2C * 2) * sizeof(float); // 67072 B
    cudaFuncSetAttribute(k_resnet, cudaFuncAttributeMaxDynamicSharedMemorySize,
                         (int)smem3);

    cudaMemcpyAsync(out, xyz, (size_t)in_sizes[0] * sizeof(float),
                    cudaMemcpyDeviceToDevice, 0);

    k_pre<<<(BB * NN) / 32, 256>>>(xyz, pts, W, bcv, g, bt, rm, rv);
    k_ball<<<(BB * NN) / 8, 256>>>();
    k_resnet<<<(BB * NN) / 128, 128, smem3>>>(
        W1, b1, g1, bt1, rm1, rv1,
        W2, b2, g2, bt2, rm2, rv2,
        pts, out + in_sizes[0]);
}

// round 8
// speedup vs baseline: 1.3039x; 1.3039x over previous
#include <cuda_runtime.h>
#include <cuda_fp16.h>
#include <cstdint>
#include <cstddef>

#define BB   8
#define NN   4096
#define KK   32
#define DD   64
#define CIN  67
#define MLPC 64
#define P1C  128
#define P2C  64
#define R2   0.04f
#define EPSF 1e-5f

// Scratch (device globals; no allocation allowed)
__device__ __half  Th_g[BB * NN * MLPC];   // fp16 s*(pts·Wd + xyz·Wx + b), 128B rows
__device__ float4  P4_g[BB * NN];          // (x, y, z, ||p||^2)
__device__ float   np_g[BB * NN * MLPC];   // max-pooled features, n-major rows
__device__ float4  sC4_g[MLPC];            // {s*Wx0, s*Wx1, s*Wx2, bt - s*rm}

// ---- f32x2 packed helpers -------------------------------------------------
__device__ __forceinline__ void ffma2(unsigned long long& d,
                                      unsigned long long a,
                                      unsigned long long b) {
    asm("fma.rn.f32x2 %0, %1, %2, %0;" : "+l"(d) : "l"(a), "l"(b));
}
__device__ __forceinline__ void fadd2(unsigned long long& d, unsigned long long a) {
    asm("add.rn.f32x2 %0, %0, %1;" : "+l"(d) : "l"(a));
}
__device__ __forceinline__ unsigned long long pack2(float lo, float hi) {
    unsigned long long r;
    asm("mov.b64 %0, {%1, %2};" : "=l"(r) : "f"(lo), "f"(hi));
    return r;
}
__device__ __forceinline__ void unpack2(unsigned long long p, float& lo, float& hi) {
    asm("mov.b64 {%0, %1}, %2;" : "=f"(lo), "=f"(hi) : "l"(p));
}

// k_pre dynamic smem layout (floats):
//   s_sh[64] | bs_sh[64] | Wsh[67*64] | Xs[67*128]   = 12992 floats = 51968 B
#define PRE_SMEM_FLOATS (MLPC + MLPC + CIN * MLPC + CIN * 128)

// ---------------------------------------------------------------------------
// K1: Tp = X[32768x67] @ Ws^T[67x64] as a register-tiled GEMM, fp16 output.
// Block = 128 threads computes 128 points x 64 outs; thread = 8 pts x 8 outs.
// ---------------------------------------------------------------------------
__global__ __launch_bounds__(128) void k_pre(
    const float* __restrict__ xyz, const float* __restrict__ pts,
    const float* __restrict__ W,   const float* __restrict__ bcv,
    const float* __restrict__ g,   const float* __restrict__ bt,
    const float* __restrict__ rm,  const float* __restrict__ rv)
{
    extern __shared__ float dsm[];
    float* s_sh  = dsm;                      // 64
    float* bs_sh = s_sh + MLPC;              // 64
    float* Wsh   = bs_sh + MLPC;             // [c][o], s-folded (67*64)
    float* Xs    = Wsh + CIN * MLPC;         // [c][m] (67*128)

    int tid = threadIdx.x;
    if (tid < MLPC) {
        float s = g[tid] / sqrtf(rv[tid] + EPSF);
        s_sh[tid]  = s;
        bs_sh[tid] = s * bcv[tid];
    }
    __syncthreads();

    // W: coalesced load, transposed + s-folded store
    for (int i = tid; i < CIN * MLPC; i += 128) {
        int o = i / CIN, c = i - o * CIN;
        Wsh[c * MLPC + o] = s_sh[o] * W[i];
    }

    int b  = blockIdx.x >> 5;              // 32 blocks per batch
    int m0 = (blockIdx.x & 31) << 7;       // 128 points per block

    // X: coalesced row copies (inputs are channel-major)
    for (int i = tid; i < CIN * 32; i += 128) {
        int c = i >> 5, j = (i & 31) << 2;
        const float* src = (c < DD) ? &pts[((b << 6) + c) * NN + m0 + j]
                                    : &xyz[(b * 3 + (c - DD)) * NN + m0 + j];
        *(float4*)&Xs[c * 128 + j] = *(const float4*)src;
    }
    __syncthreads();

    // candidate table entry for this block's 128 points
    {
        float x = Xs[64 * 128 + tid], y = Xs[65 * 128 + tid], z = Xs[66 * 128 + tid];
        P4_g[b * NN + m0 + tid] = make_float4(x, y, z, fmaf(z, z, fmaf(y, y, x * x)));
    }
    if (blockIdx.x == 0 && tid < MLPC)
        sC4_g[tid] = make_float4(Wsh[64 * MLPC + tid], Wsh[65 * MLPC + tid],
                                 Wsh[66 * MLPC + tid],
                                 bt[tid] - s_sh[tid] * rm[tid]);

    int om = tid & 7;        // 8 out-groups of 8
    int pm = tid >> 3;       // 16 point-groups of 8

    unsigned long long acc[8][4];
#pragma unroll
    for (int p = 0; p < 8; p++)
#pragma unroll
        for (int q = 0; q < 4; q++) acc[p][q] = 0ull;

    const float* wp = &Wsh[om * 8];
    const float* xp = &Xs[pm * 8];

#pragma unroll 1
    for (int c = 0; c < CIN; c++) {
        float4 w0 = *(const float4*)(wp + c * MLPC);
        float4 w1 = *(const float4*)(wp + c * MLPC + 4);
        float4 x0 = *(const float4*)(xp + c * 128);
        float4 x1 = *(const float4*)(xp + c * 128 + 4);
        unsigned long long wv[4] = { pack2(w0.x, w0.y), pack2(w0.z, w0.w),
                                     pack2(w1.x, w1.y), pack2(w1.z, w1.w) };
        float xv[8] = { x0.x, x0.y, x0.z, x0.w, x1.x, x1.y, x1.z, x1.w };
#pragma unroll
        for (int p = 0; p < 8; p++) {
            unsigned long long xx = pack2(xv[p], xv[p]);
#pragma unroll
            for (int q = 0; q < 4; q++) ffma2(acc[p][q], wv[q], xx);
        }
    }

    // bias + fp16 convert + 16B store per point
    float bsv[8];
#pragma unroll
    for (int q = 0; q < 8; q++) bsv[q] = bs_sh[om * 8 + q];

#pragma unroll
    for (int p = 0; p < 8; p++) {
        int gm = b * NN + m0 + pm * 8 + p;
        union { __half2 h2[4]; uint4 u4; } cvt;
#pragma unroll
        for (int q = 0; q < 4; q++) {
            float lo, hi;
            unpack2(acc[p][q], lo, hi);
            cvt.h2[q] = __floats2half2_rn(lo + bsv[2 * q], hi + bsv[2 * q + 1]);
        }
        *((uint4*)Th_g + (size_t)gm * 8 + om) = cvt.u4;
    }
}

// ---------------------------------------------------------------------------
// K2: warp-autonomous ball query (64 candidates/iter) + fp16 gather-max
// ---------------------------------------------------------------------------
__global__ __launch_bounds__(256) void k_ball()
{
    __shared__ int gi_sh[8][KK];

    int tid  = threadIdx.x;
    int w    = tid >> 5;
    int lane = tid & 31;
    unsigned below = (1u << lane) - 1u;

    int b  = blockIdx.x >> 9;                   // 512 blocks per batch
    int n  = ((blockIdx.x & 511) << 3) + w;
    int bN = b * NN;

    float4 q = P4_g[bN + n];

    int cnt = 0;
#pragma unroll 1
    for (int base = 0; base < NN; base += 64) {
        float4 c0 = __ldg(&P4_g[bN + base + lane]);
        float4 c1 = __ldg(&P4_g[bN + base + 32 + lane]);

        float d0 = q.w + c0.w - 2.0f * fmaf(q.z, c0.z, fmaf(q.y, c0.y, q.x * c0.x));
        float d1 = q.w + c1.w - 2.0f * fmaf(q.z, c1.z, fmaf(q.y, c1.y, q.x * c1.x));

        unsigned m0 = __ballot_sync(0xffffffffu, d0 <= R2);
        unsigned m1 = __ballot_sync(0xffffffffu, d1 <= R2);

        if (d0 <= R2) {
            int pos = cnt + __popc(m0 & below);
            if (pos < KK) gi_sh[w][pos] = base + lane;
        }
        int n0 = __popc(m0);
        if (d1 <= R2) {
            int pos = cnt + n0 + __popc(m1 & below);
            if (pos < KK) gi_sh[w][pos] = base + 32 + lane;
        }
        cnt += n0 + __popc(m1);
        if (cnt >= KK) break;
    }
    __syncwarp();

    int cap   = (cnt < KK) ? cnt : KK;
    int gidx0 = gi_sh[w][0];

    __half2 mx = __float2half2_rn(-65504.0f);
#pragma unroll
    for (int j = 0; j < KK; j++) {
        int gj = (j < cap) ? gi_sh[w][j] : gidx0;
        const __half2* tr = ((const __half2*)Th_g) + (((size_t)(bN + gj)) << 5) + lane;
        mx = __hmax2(mx, __ldg(tr));
    }
    float2 m = __half22float2(mx);

    float4 a0 = sC4_g[2 * lane];
    float4 a1 = sC4_g[2 * lane + 1];
    float u0 = a0.w - fmaf(a0.z, q.z, fmaf(a0.y, q.y, a0.x * q.x));
    float u1 = a1.w - fmaf(a1.z, q.z, fmaf(a1.y, q.y, a1.x * q.x));

    float2 outv = make_float2(fmaxf(m.x + u0, 0.0f), fmaxf(m.y + u1, 0.0f));
    *(float2*)&np_g[((size_t)(bN + n)) * MLPC + 2 * lane] = outv;
}

// ---------------------------------------------------------------------------
// K3: pointwise resnet 64->128->64 + residual ReLU, f32x2 packed FMA
// ---------------------------------------------------------------------------
__global__ __launch_bounds__(128) void k_resnet(
    const float* __restrict__ W1, const float* __restrict__ b1,
    const float* __restrict__ g1, const float* __restrict__ bt1,
    const float* __restrict__ rm1, const float* __restrict__ rv1,
    const float* __restrict__ W2, const float* __restrict__ b2,
    const float* __restrict__ g2, const float* __restrict__ bt2,
    const float* __restrict__ rm2, const float* __restrict__ rv2,
    const float* __restrict__ pts, float* __restrict__ out)
{
    extern __shared__ float sm[];
    float* W1sh  = sm;                  // [128][64] row-major
    float* W2Tsh = sm + P1C * P2C;      // [o][p] (W2 transposed)
    float* s1sh  = W2Tsh + P1C * P2C;
    float* t1sh  = s1sh + P1C;
    float* s2sh  = t1sh + P1C;
    float* t2sh  = s2sh + P2C;

    int tid = threadIdx.x;
    for (int i = tid; i < P1C * P2C; i += 128) {
        W1sh[i] = W1[i];
        W2Tsh[(i & (P1C - 1)) * P2C + (i >> 7)] = W2[i];
    }
    if (tid < P1C) {
        float s = g1[tid] / sqrtf(rv1[tid] + EPSF);
        s1sh[tid] = s;
        t1sh[tid] = fmaf(s, b1[tid] - rm1[tid], bt1[tid]);
    }
    if (tid < P2C) {
        float s = g2[tid] / sqrtf(rv2[tid] + EPSF);
        s2sh[tid] = s;
        t2sh[tid] = fmaf(s, b2[tid] - rm2[tid], bt2[tid]);
    }
    __syncthreads();

    int pt = blockIdx.x * 128 + tid;
    int b  = pt >> 12;
    int n  = pt & (NN - 1);

    unsigned long long v2[32];
    {
        const ulonglong2* vr = (const ulonglong2*)(np_g + (size_t)pt * MLPC);
#pragma unroll
        for (int i = 0; i < 16; i++) {
            ulonglong2 t = vr[i];
            v2[2 * i] = t.x;
            v2[2 * i + 1] = t.y;
        }
    }

    unsigned long long ap[32];
#pragma unroll
    for (int i = 0; i < 32; i++) ap[i] = 0ull;

#pragma unroll 2
    for (int o = 0; o < P1C; o++) {
        const ulonglong2* w1r = (const ulonglong2*)(W1sh + o * P2C);
        unsigned long long hp0 = 0ull, hp1 = 0ull, hp2 = 0ull, hp3 = 0ull;
#pragma unroll
        for (int i = 0; i < 8; i++) {
            ulonglong2 wa = w1r[2 * i];
            ulonglong2 wb = w1r[2 * i + 1];
            ffma2(hp0, wa.x, v2[4 * i + 0]);
            ffma2(hp1, wa.y, v2[4 * i + 1]);
            ffma2(hp2, wb.x, v2[4 * i + 2]);
            ffma2(hp3, wb.y, v2[4 * i + 3]);
        }
        fadd2(hp0, hp1);
        fadd2(hp2, hp3);
        fadd2(hp0, hp2);
        float hl, hh;
        unpack2(hp0, hl, hh);
        float h  = hl + hh;
        float x1 = fmaxf(fmaf(s1sh[o], h, t1sh[o]), 0.0f);
        unsigned long long X = pack2(x1, x1);

        const ulonglong2* w2r = (const ulonglong2*)(W2Tsh + o * P2C);
#pragma unroll
        for (int i = 0; i < 16; i++) {
            ulonglong2 wt = w2r[i];
            ffma2(ap[2 * i + 0], wt.x, X);
            ffma2(ap[2 * i + 1], wt.y, X);
        }
    }

#pragma unroll
    for (int i = 0; i < 32; i++) {
        float a0, a1;
        unpack2(ap[i], a0, a1);
        int p0 = 2 * i, p1 = 2 * i + 1;
        float v0 = fmaf(s2sh[p0], a0, t2sh[p0]) + pts[(b * P2C + p0) * NN + n];
        float v1 = fmaf(s2sh[p1], a1, t2sh[p1]) + pts[(b * P2C + p1) * NN + n];
        out[(b * P2C + p0) * NN + n] = fmaxf(v0, 0.0f);
        out[(b * P2C + p1) * NN + n] = fmaxf(v1, 0.0f);
    }
}

// ---------------------------------------------------------------------------
// Launch
// ---------------------------------------------------------------------------
extern "C" void kernel_launch(void* const* d_in, const int* in_sizes, int n_in,
                              void* d_out, int out_size)
{
    (void)n_in; (void)out_size;

    const float* xyz = (const float*)d_in[0];
    const float* pts = (const float*)d_in[1];
    const float* W   = (const float*)d_in[2];
    const float* bcv = (const float*)d_in[3];
    const float* g   = (const float*)d_in[4];
    const float* bt  = (const float*)d_in[5];
    const float* rm  = (const float*)d_in[6];
    const float* rv  = (const float*)d_in[7];
    const float* W1  = (const float*)d_in[8];
    const float* b1  = (const float*)d_in[9];
    const float* g1  = (const float*)d_in[10];
    const float* bt1 = (const float*)d_in[11];
    const float* rm1 = (const float*)d_in[12];
    const float* rv1 = (const float*)d_in[13];
    const float* W2  = (const float*)d_in[14];
    const float* b2  = (const float*)d_in[15];
    const float* g2  = (const float*)d_in[16];
    const float* bt2 = (const float*)d_in[17];
    const float* rm2 = (const float*)d_in[18];
    const float* rv2 = (const float*)d_in[19];

    float* out = (float*)d_out;

    static const size_t smem1 = (size_t)PRE_SMEM_FLOATS * sizeof(float); // 51968 B
    static const size_t smem3 =
        (size_t)(P1C * P2C * 2 + P1C * 2 + P2C * 2) * sizeof(float);     // 67072 B
    cudaFuncSetAttribute(k_pre, cudaFuncAttributeMaxDynamicSharedMemorySize,
                         (int)smem1);
    cudaFuncSetAttribute(k_resnet, cudaFuncAttributeMaxDynamicSharedMemorySize,
                         (int)smem3);

    cudaMemcpyAsync(out, xyz, (size_t)in_sizes[0] * sizeof(float),
                    cudaMemcpyDeviceToDevice, 0);

    k_pre<<<(BB * NN) / 128, 128, smem1>>>(xyz, pts, W, bcv, g, bt, rm, rv);
    k_ball<<<(BB * NN) / 8, 256>>>();
    k_resnet<<<(BB * NN) / 128, 128, smem3>>>(
        W1, b1, g1, bt1, rm1, rv1,
        W2, b2, g2, bt2, rm2, rv2,
        pts, out + in_sizes[0]);
}